// round 6
// baseline (speedup 1.0000x reference)
#include <cuda_runtime.h>

// MultiLayerRNNModel: 2-layer tanh RNN, T=2048, B=4096, I=3, H=5
// out = concat(out[T,B,H], h_n[2,B,H])
//
// R6: warp-specialized layer split. 16-warp blocks: even warps compute
// layer-0 units, odd warps layer-1 units, software-pipelined one step apart
// (step t: L0 makes h0(t), L1 makes h1(t-1)). States cross via a double-
// buffered smem slab with ONE __syncthreads per step. 2048 warps total
// (3.46/SMSP) vs 1024 in the best prior kernel, with ~half the work per
// warp: latency hiding doubles while per-warp issue halves.
// 128 blocks x 512 threads -> exactly <=1 block/SM, single wave.

#define T_LEN   2048
#define B_SZ    4096
#define XSTRIDE (B_SZ * 3)
#define OSTRIDE (B_SZ * 5)

__device__ __forceinline__ float tanh_fast(float v) {
    float y;
    asm("tanh.approx.f32 %0, %1;" : "=f"(y) : "f"(v));
    return y;
}

__global__ __launch_bounds__(512, 1)
void rnn2_kernel(const float* __restrict__ x,
                 const float* __restrict__ hx,
                 const float* __restrict__ w_ih0,
                 const float* __restrict__ w_hh0,
                 const float* __restrict__ b_ih0,
                 const float* __restrict__ b_hh0,
                 const float* __restrict__ w_ih1,
                 const float* __restrict__ w_hh1,
                 const float* __restrict__ b_ih1,
                 const float* __restrict__ b_hh1,
                 float* __restrict__ out)
{
    // buf[parity][slot][0..4] = h0, [5..9] = h1, [10..11] pad (48B stride,
    // float4-aligned; 4 slots/warp broadcast-read -> conflict-free).
    __shared__ __align__(16) float buf[2][32][12];

    const int warp = threadIdx.x >> 5;
    const int lane = threadIdx.x & 31;
    const int pair = warp >> 1;
    const int role = warp & 1;            // 0 = layer 0, 1 = layer 1
    const int bi   = lane >> 3;           // batch within pair: 0..3
    const int j    = lane & 7;            // hidden unit (active j<5)
    const int slot = pair * 4 + bi;       // 0..31
    const int b    = blockIdx.x * 32 + slot;
    const bool act = (j < 5);
    const int  jj  = act ? j : 0;

    // role-specific weights (row jj)
    float wi0[3], wh0[5], bias0 = 0.f;
    float wi1[5], wh1[5], bias1 = 0.f;
    float h0j = 0.f, h1j = 0.f;
    const float* xb = x + b * 3;
    float*       op = out + b * 5 + j;
    float xq[4][3];

    if (role == 0) {
        #pragma unroll
        for (int k = 0; k < 3; k++) wi0[k] = w_ih0[jj * 3 + k];
        #pragma unroll
        for (int k = 0; k < 5; k++) wh0[k] = w_hh0[jj * 5 + k];
        bias0 = b_ih0[jj] + b_hh0[jj];
        // x queue holds x(0..3)
        #pragma unroll
        for (int p = 0; p < 4; p++) {
            const float* xp = xb + p * XSTRIDE;
            xq[p][0] = xp[0]; xq[p][1] = xp[1]; xq[p][2] = xp[2];
        }
        // ---- prologue: h0(0) from hx0 (registers) + x(0) ----
        float h0i[5];
        #pragma unroll
        for (int k = 0; k < 5; k++) h0i[k] = hx[b * 5 + k];
        const float xp_ = fmaf(wi0[2], xq[0][2],
                          fmaf(wi0[1], xq[0][1],
                          fmaf(wi0[0], xq[0][0], bias0)));
        const float a0 = fmaf(wh0[0], h0i[0], xp_);
        const float a1 = fmaf(wh0[2], h0i[2], wh0[1] * h0i[1]);
        const float a2 = fmaf(wh0[4], h0i[4], wh0[3] * h0i[3]);
        h0j = tanh_fast((a0 + a1) + a2);
        if (act) buf[0][slot][j] = h0j;
        // refill phase 0 with x(4)
        const float* xp4 = xb + 4 * XSTRIDE;
        xq[0][0] = xp4[0]; xq[0][1] = xp4[1]; xq[0][2] = xp4[2];
    } else {
        #pragma unroll
        for (int k = 0; k < 5; k++) {
            wi1[k] = w_ih1[jj * 5 + k];
            wh1[k] = w_hh1[jj * 5 + k];
        }
        bias1 = b_ih1[jj] + b_hh1[jj];
        // seed h1(-1) = hx1 into buffer 0
        if (act) buf[0][slot][5 + j] = hx[B_SZ * 5 + b * 5 + j];
    }
    __syncthreads();

// L0 step t: h0(t) = tanh(Wih0 x(t) + b0 + Whh0 h0(t-1)). XP = t&3 literal.
#define L0STEP(t, XP, WP, RP) {                                               \
    const float4 q  = *(const float4*)&buf[RP][slot][0];                      \
    const float  q4 = buf[RP][slot][4];                                       \
    const float xp_ = fmaf(wi0[2], xq[XP][2],                                 \
                      fmaf(wi0[1], xq[XP][1],                                 \
                      fmaf(wi0[0], xq[XP][0], bias0)));                       \
    if ((t) + 4 < T_LEN) {                                                    \
        const float* xp = xb + ((t) + 4) * XSTRIDE;                           \
        xq[XP][0] = xp[0]; xq[XP][1] = xp[1]; xq[XP][2] = xp[2];              \
    }                                                                         \
    const float a0 = fmaf(wh0[0], q.x, xp_);                                  \
    const float a1 = fmaf(wh0[2], q.z, wh0[1] * q.y);                         \
    const float a2 = fmaf(wh0[4], q4,  wh0[3] * q.w);                         \
    h0j = tanh_fast((a0 + a1) + a2);                                          \
    if (act) buf[WP][slot][j] = h0j;                                          \
}

// L1 step t: h1(t-1) = tanh(Wih1 h0(t-1) + b1 + Whh1 h1(t-2)).
#define L1STEP(t, WP, RP) {                                                   \
    const float4 qa = *(const float4*)&buf[RP][slot][0];  /* h0[0..3] */      \
    const float4 qb = *(const float4*)&buf[RP][slot][4];  /* h0[4],h1[0..2]*/ \
    const float2 qc = *(const float2*)&buf[RP][slot][8];  /* h1[3..4] */      \
    const float ua = fmaf(wi1[2], qa.z,                                       \
                     fmaf(wi1[1], qa.y,                                       \
                     fmaf(wi1[0], qa.x, bias1)));                             \
    const float ub = fmaf(wi1[4], qb.x, wi1[3] * qa.w);                       \
    const float va = fmaf(wh1[1], qb.z, wh1[0] * qb.y);                       \
    const float vb = fmaf(wh1[4], qc.y, fmaf(wh1[3], qc.x, wh1[2] * qb.w));   \
    h1j = tanh_fast((ua + ub) + (va + vb));                                   \
    if (act) {                                                                \
        buf[WP][slot][5 + j] = h1j;                                           \
        op[((t) - 1) * OSTRIDE] = h1j;                                        \
    }                                                                         \
}

// One full step for the block. WP = t&1, RP = 1-WP, XP = t&3 (all literal).
#define FULLSTEP(t, XP, WP, RP)                                               \
    if (role == 0) { L0STEP(t, XP, WP, RP) } else { L1STEP(t, WP, RP) }       \
    __syncthreads();

    // ---- main loop: t = 1 .. 2044 (t0 = 4m+1) ----
    for (int t0 = 1; t0 < 2045; t0 += 4) {
        FULLSTEP(t0 + 0, 1, 1, 0);
        FULLSTEP(t0 + 1, 2, 0, 1);
        FULLSTEP(t0 + 2, 3, 1, 0);
        FULLSTEP(t0 + 3, 0, 0, 1);
    }
    // ---- tail: t = 2045, 2046, 2047 ----
    FULLSTEP(2045, 1, 1, 0);
    FULLSTEP(2046, 2, 0, 1);
    FULLSTEP(2047, 3, 1, 0);

    // ---- epilogue ----
    if (role == 1) {
        // buf[1] = {h0(2047), h1(2046)} -> h1(2047)
        const float4 qa = *(const float4*)&buf[1][slot][0];
        const float4 qb = *(const float4*)&buf[1][slot][4];
        const float2 qc = *(const float2*)&buf[1][slot][8];
        const float ua = fmaf(wi1[2], qa.z,
                         fmaf(wi1[1], qa.y,
                         fmaf(wi1[0], qa.x, bias1)));
        const float ub = fmaf(wi1[4], qb.x, wi1[3] * qa.w);
        const float va = fmaf(wh1[1], qb.z, wh1[0] * qb.y);
        const float vb = fmaf(wh1[4], qc.y, fmaf(wh1[3], qc.x, wh1[2] * qb.w));
        h1j = tanh_fast((ua + ub) + (va + vb));
        if (act) {
            op[(T_LEN - 1) * OSTRIDE]          = h1j;   // out[2047]
            op[T_LEN * OSTRIDE + OSTRIDE]      = h1j;   // h_n[1]
        }
    } else {
        if (act) op[T_LEN * OSTRIDE] = h0j;             // h_n[0] = h0(2047)
    }
#undef FULLSTEP
#undef L0STEP
#undef L1STEP
}

extern "C" void kernel_launch(void* const* d_in, const int* in_sizes, int n_in,
                              void* d_out, int out_size)
{
    const float* x     = (const float*)d_in[0];
    const float* hx    = (const float*)d_in[1];
    const float* w_ih0 = (const float*)d_in[2];
    const float* w_hh0 = (const float*)d_in[3];
    const float* b_ih0 = (const float*)d_in[4];
    const float* b_hh0 = (const float*)d_in[5];
    const float* w_ih1 = (const float*)d_in[6];
    const float* w_hh1 = (const float*)d_in[7];
    const float* b_ih1 = (const float*)d_in[8];
    const float* b_hh1 = (const float*)d_in[9];
    float* out = (float*)d_out;

    // 128 blocks x 512 threads = 2048 warps; 32 batches per block.
    rnn2_kernel<<<128, 512>>>(x, hx, w_ih0, w_hh0, b_ih0, b_hh0,
                              w_ih1, w_hh1, b_ih1, b_hh1, out);
}

// round 7
// speedup vs baseline: 2.1557x; 2.1557x over previous
#include <cuda_runtime.h>

// MultiLayerRNNModel: 2-layer tanh RNN, T=2048, B=4096, I=3, H=5
// out = concat(out[T,B,H], h_n[2,B,H])
//
// R7: hybrid. Layer 0 is computed REDUNDANTLY in every lane with packed
// fma.rn.f32x2 (pairs (0,1),(2,3),(4,dup)) -> the h0->h0 recurrence is
// register-only (no STS/sync/LDS in its loop, chain ~44 cyc). Layer 1 stays
// lane-split (lane j owns unit j) with a smem broadcast of only h1; its
// wi1.h0 half is precomputed off-path (u_part) as soon as h0(t) is ready.
// Software pipelined: step t computes h0(t) and h1(t-1). One syncwarp/step.
// Geometry as R3: 8 lanes/batch, 147 blocks x 224 threads = 1024+ warps.

#define T_LEN   2048
#define B_SZ    4096
#define XSTRIDE (B_SZ * 3)
#define OSTRIDE (B_SZ * 5)

typedef unsigned long long ull;

__device__ __forceinline__ float tanh_fast(float v) {
    float y;
    asm("tanh.approx.f32 %0, %1;" : "=f"(y) : "f"(v));
    return y;
}
__device__ __forceinline__ ull pk2(float lo, float hi) {
    ull r;
    asm("mov.b64 %0, {%1, %2};" : "=l"(r) : "f"(lo), "f"(hi));
    return r;
}
__device__ __forceinline__ ull splat2(float v) { return pk2(v, v); }
__device__ __forceinline__ ull fma2(ull a, ull b, ull c) {
    ull d;
    asm("fma.rn.f32x2 %0, %1, %2, %3;" : "=l"(d) : "l"(a), "l"(b), "l"(c));
    return d;
}
__device__ __forceinline__ ull mul2(ull a, ull b) {
    ull d;
    asm("mul.rn.f32x2 %0, %1, %2;" : "=l"(d) : "l"(a), "l"(b));
    return d;
}
__device__ __forceinline__ ull add2(ull a, ull b) {
    ull d;
    asm("add.rn.f32x2 %0, %1, %2;" : "=l"(d) : "l"(a), "l"(b));
    return d;
}
__device__ __forceinline__ float lo2(ull v) {
    float a;
    asm("{ .reg .b32 hi; mov.b64 {%0, hi}, %1; }" : "=f"(a) : "l"(v));
    return a;
}
__device__ __forceinline__ float hi2(ull v) {
    float a;
    asm("{ .reg .b32 lo; mov.b64 {lo, %0}, %1; }" : "=f"(a) : "l"(v));
    return a;
}

__global__ __launch_bounds__(224, 1)
void rnn2_kernel(const float* __restrict__ x,
                 const float* __restrict__ hx,
                 const float* __restrict__ w_ih0,
                 const float* __restrict__ w_hh0,
                 const float* __restrict__ b_ih0,
                 const float* __restrict__ b_hh0,
                 const float* __restrict__ w_ih1,
                 const float* __restrict__ w_hh1,
                 const float* __restrict__ b_ih1,
                 const float* __restrict__ b_hh1,
                 float* __restrict__ out)
{
    // h1 broadcast: 8-float slots; warp's 4 groups at 32B spacing ->
    // LDS.128 bases hit banks {0,8,16,24}: conflict-free broadcast.
    __shared__ __align__(16) float buf[2][28][8];

    const int tid = blockIdx.x * 224 + threadIdx.x;
    const int b   = tid >> 3;
    const int j   = threadIdx.x & 7;
    const int g   = threadIdx.x >> 3;          // group in block: 0..27
    const bool bval = (b < B_SZ);
    const bool act  = bval && (j < 5);
    const int  jj   = (j < 5) ? j : 0;

    // ---- packed layer-0 weights (identical in every lane) ----
    ull WI0[3][3], WH0[3][5], B0[3];
    #pragma unroll
    for (int v = 0; v < 3; v++) {
        const int j0 = 2 * v;
        const int j1 = (2 * v + 1 < 5) ? 2 * v + 1 : 4;
        #pragma unroll
        for (int i = 0; i < 3; i++)
            WI0[v][i] = pk2(w_ih0[j0 * 3 + i], w_ih0[j1 * 3 + i]);
        #pragma unroll
        for (int k = 0; k < 5; k++)
            WH0[v][k] = pk2(w_hh0[j0 * 5 + k], w_hh0[j1 * 5 + k]);
        B0[v] = pk2(b_ih0[j0] + b_hh0[j0], b_ih0[j1] + b_hh0[j1]);
    }
    // ---- layer-1 scalar weights (row jj) ----
    float wi1[5], wh1[5];
    #pragma unroll
    for (int k = 0; k < 5; k++) {
        wi1[k] = w_ih1[jj * 5 + k];
        wh1[k] = w_hh1[jj * 5 + k];
    }
    const float bias1 = b_ih1[jj] + b_hh1[jj];

    // ---- state ----
    ull  S[5];          // splatted h0(t-1), identical in all lanes
    float tq0, tq1, tq2, tq3, tq4;   // scalar h0(t-1)
    float h1v[5];       // h1(t-2) full vector
    float u_part = 0.f; // bias1 + wi1 . h0(t-1)
    #pragma unroll
    for (int k = 0; k < 5; k++) {
        const float h0i = bval ? hx[b * 5 + k]            : 0.f;
        h1v[k]          = bval ? hx[B_SZ * 5 + b * 5 + k] : 0.f;
        S[k] = splat2(h0i);
    }

    const float* xb   = x + b * 3;
    float*       outp = out + b * 5 + j;

    // x prefetch queue, slot p holds x[t] with t&7 == p
    float xq[8][3];
    #pragma unroll
    for (int p = 0; p < 8; p++) {
        const float* xp = xb + p * XSTRIDE;
        xq[p][0] = bval ? xp[0] : 0.f;
        xq[p][1] = bval ? xp[1] : 0.f;
        xq[p][2] = bval ? xp[2] : 0.f;
    }

// Packed layer-0 update from x phase XP: S,tq <- h0(t); u_part <- wi1.h0(t).
#define L0(XP) {                                                              \
    const ull X0 = splat2(xq[XP][0]), X1 = splat2(xq[XP][1]),                 \
              X2 = splat2(xq[XP][2]);                                         \
    ull A0, A1, A2;                                                           \
    {                                                                         \
        const ull c1 = fma2(WI0[0][2], X2, fma2(WI0[0][1], X1,                \
                       fma2(WI0[0][0], X0, B0[0])));                          \
        const ull c2 = fma2(WH0[0][4], S[4], fma2(WH0[0][3], S[3],            \
                       fma2(WH0[0][2], S[2], fma2(WH0[0][1], S[1],            \
                       mul2(WH0[0][0], S[0])))));                             \
        A0 = add2(c1, c2);                                                    \
    }                                                                         \
    {                                                                         \
        const ull c1 = fma2(WI0[1][2], X2, fma2(WI0[1][1], X1,                \
                       fma2(WI0[1][0], X0, B0[1])));                          \
        const ull c2 = fma2(WH0[1][4], S[4], fma2(WH0[1][3], S[3],            \
                       fma2(WH0[1][2], S[2], fma2(WH0[1][1], S[1],            \
                       mul2(WH0[1][0], S[0])))));                             \
        A1 = add2(c1, c2);                                                    \
    }                                                                         \
    {                                                                         \
        const ull c1 = fma2(WI0[2][2], X2, fma2(WI0[2][1], X1,                \
                       fma2(WI0[2][0], X0, B0[2])));                          \
        const ull c2 = fma2(WH0[2][4], S[4], fma2(WH0[2][3], S[3],            \
                       fma2(WH0[2][2], S[2], fma2(WH0[2][1], S[1],            \
                       mul2(WH0[2][0], S[0])))));                             \
        A2 = add2(c1, c2);                                                    \
    }                                                                         \
    tq0 = tanh_fast(lo2(A0));                                                 \
    tq1 = tanh_fast(hi2(A0));                                                 \
    tq2 = tanh_fast(lo2(A1));                                                 \
    tq3 = tanh_fast(hi2(A1));                                                 \
    tq4 = tanh_fast(lo2(A2));                                                 \
    S[0] = splat2(tq0); S[1] = splat2(tq1); S[2] = splat2(tq2);               \
    S[3] = splat2(tq3); S[4] = splat2(tq4);                                   \
    u_part = fmaf(wi1[4], tq4, fmaf(wi1[3], tq3, fmaf(wi1[2], tq2,            \
             fmaf(wi1[1], tq1, fmaf(wi1[0], tq0, bias1)))));                  \
}

// One pipelined step t: h1(t-1) from (u_part, h1v), then h0(t) via L0.
// XP == t&7, BP == t&1, both literal.
#define STEP(t, XP, BP) {                                                     \
    /* h1(t-1): comm chain */                                                 \
    const float va = fmaf(wh1[1], h1v[1], fmaf(wh1[0], h1v[0], u_part));      \
    const float vb = fmaf(wh1[3], h1v[3], wh1[2] * h1v[2]);                   \
    const float u  = fmaf(wh1[4], h1v[4], va + vb);                           \
    const float h1j = tanh_fast(u);                                           \
    if (act) {                                                                \
        buf[BP][g][j] = h1j;                                                  \
        outp[((t) - 1) * OSTRIDE] = h1j;                                      \
    }                                                                         \
    /* h0(t): register-only packed update (also refreshes u_part) */          \
    L0(XP);                                                                   \
    if (bval && (t) + 8 < T_LEN) {                                            \
        const float* xp = xb + ((t) + 8) * XSTRIDE;                           \
        xq[XP][0] = xp[0]; xq[XP][1] = xp[1]; xq[XP][2] = xp[2];              \
    }                                                                         \
    __syncwarp();                                                             \
    {                                                                         \
        const float4 qa = *(const float4*)&buf[BP][g][0];                     \
        h1v[0] = qa.x; h1v[1] = qa.y; h1v[2] = qa.z; h1v[3] = qa.w;           \
        h1v[4] = buf[BP][g][4];                                               \
    }                                                                         \
}

    // ---- prologue: h0(0) + u_part; h1v already = hx1 ----
    L0(0);
    if (bval) {
        const float* xp = xb + 8 * XSTRIDE;
        xq[0][0] = xp[0]; xq[0][1] = xp[1]; xq[0][2] = xp[2];
    }

    // ---- main loop: t = 1 .. 2040 (t0 = 8m+1) ----
    for (int t0 = 1; t0 < 2041; t0 += 8) {
        STEP(t0 + 0, 1, 1);
        STEP(t0 + 1, 2, 0);
        STEP(t0 + 2, 3, 1);
        STEP(t0 + 3, 4, 0);
        STEP(t0 + 4, 5, 1);
        STEP(t0 + 5, 6, 0);
        STEP(t0 + 6, 7, 1);
        STEP(t0 + 7, 0, 0);
    }
    // ---- tail: t = 2041 .. 2047 ----
    STEP(2041, 1, 1);
    STEP(2042, 2, 0);
    STEP(2043, 3, 1);
    STEP(2044, 4, 0);
    STEP(2045, 5, 1);
    STEP(2046, 6, 0);
    STEP(2047, 7, 1);

    // ---- epilogue: h1(2047) from u_part (wi1.h0(2047)) + wh1.h1(2046) ----
    {
        const float va = fmaf(wh1[1], h1v[1], fmaf(wh1[0], h1v[0], u_part));
        const float vb = fmaf(wh1[3], h1v[3], wh1[2] * h1v[2]);
        const float u  = fmaf(wh1[4], h1v[4], va + vb);
        const float h1j = tanh_fast(u);
        const float hn0 = (jj == 0) ? tq0 : (jj == 1) ? tq1 :
                          (jj == 2) ? tq2 : (jj == 3) ? tq3 : tq4;
        if (act) {
            outp[(T_LEN - 1) * OSTRIDE]     = h1j;   // out[2047]
            outp[T_LEN * OSTRIDE]           = hn0;   // h_n[0] = h0(2047)
            outp[T_LEN * OSTRIDE + OSTRIDE] = h1j;   // h_n[1] = h1(2047)
        }
    }
#undef STEP
#undef L0
}

extern "C" void kernel_launch(void* const* d_in, const int* in_sizes, int n_in,
                              void* d_out, int out_size)
{
    const float* x     = (const float*)d_in[0];
    const float* hx    = (const float*)d_in[1];
    const float* w_ih0 = (const float*)d_in[2];
    const float* w_hh0 = (const float*)d_in[3];
    const float* b_ih0 = (const float*)d_in[4];
    const float* b_hh0 = (const float*)d_in[5];
    const float* w_ih1 = (const float*)d_in[6];
    const float* w_hh1 = (const float*)d_in[7];
    const float* b_ih1 = (const float*)d_in[8];
    const float* b_hh1 = (const float*)d_in[9];
    float* out = (float*)d_out;

    const int threads = 224;                                 // 7 warps
    const int blocks  = (B_SZ * 8 + threads - 1) / threads;  // 147

    rnn2_kernel<<<blocks, threads>>>(x, hx, w_ih0, w_hh0, b_ih0, b_hh0,
                                     w_ih1, w_hh1, b_ih1, b_hh1, out);
}